// round 15
// baseline (speedup 1.0000x reference)
#include <cuda_runtime.h>

#define H     20
#define SEQ   512
#define NB    4096
#define WARPS 4
#define THREADS (WARPS * 32)
#define GRID  (NB / WARPS)     // 1024

typedef unsigned long long u64;
typedef unsigned int u32;

__device__ __forceinline__ u64 pack2(float a, float b) {
    u64 r; asm("mov.b64 %0, {%1,%2};" : "=l"(r) : "f"(a), "f"(b)); return r;
}
__device__ __forceinline__ void unpack2(u64 v, float& a, float& b) {
    asm("mov.b64 {%0,%1}, %2;" : "=f"(a), "=f"(b) : "l"(v));
}
// Blackwell packed fp32 FMA (f32x2, PTX-only)
__device__ __forceinline__ u64 fma2(u64 a, u64 b, u64 c) {
    u64 d; asm("fma.rn.f32x2 %0, %1, %2, %3;" : "=l"(d) : "l"(a), "l"(b), "l"(c)); return d;
}
// HW tanh (MUFU.TANH) — measured safe: rel_err 1.56e-6 over the 512-step recurrence
__device__ __forceinline__ float tanh_ap(float v) {
    float r; asm("tanh.approx.f32 %0, %1;" : "=f"(r) : "f"(v)); return r;
}
__device__ __forceinline__ float sigmoid_ap(float v) {
    return fmaf(0.5f, tanh_ap(0.5f * v), 0.5f);   // FMUL + MUFU + FFMA
}

__global__ __launch_bounds__(THREADS, 5) void lstm_fused(
    const float* __restrict__ x,     const float* __restrict__ W_ih,
    const float* __restrict__ W_hh,  const float* __restrict__ b_ih,
    const float* __restrict__ b_hh,  const float* __restrict__ W_lin,
    const float* __restrict__ b_lin, float* __restrict__ out)
{
    // Per-warp double-buffered h, duplicated {h,h} so LDS.128 feeds fma2.
    __shared__ __align__(16) float2 hbuf[WARPS][2][H];
    // Biases + x-weights: reloaded per step (2 broadcast LDS) to free 8 regs.
    // bw[j] = {bif, bgo}; bw[H+j] = {wxif, wxgo}
    __shared__ __align__(16) ulonglong2 bw[2 * H];
    __shared__ float xs[WARPS * SEQ];    // staged x rows (8 KB)

    const int warp = threadIdx.x >> 5;
    const int lane = threadIdx.x & 31;
    const int batch = blockIdx.x * WARPS + warp;
    const int j = (lane < H) ? lane : (H - 1);   // clamp idle lanes

    // Coalesced stage of x for all 4 batches of this block.
    for (int i = threadIdx.x; i < WARPS * (SEQ / 4); i += THREADS)
        ((float4*)xs)[i] = ((const float4*)(x + (size_t)blockIdx.x * WARPS * SEQ))[i];

    if (threadIdx.x < H) {
        int jj = threadIdx.x;
        bw[jj].x     = pack2(b_ih[jj] + b_hh[jj],           b_ih[H + jj] + b_hh[H + jj]);
        bw[jj].y     = pack2(b_ih[2 * H + jj] + b_hh[2 * H + jj],
                             b_ih[3 * H + jj] + b_hh[3 * H + jj]);
        bw[H + jj].x = pack2(W_ih[jj],         W_ih[H + jj]);
        bw[H + jj].y = pack2(W_ih[2 * H + jj], W_ih[3 * H + jj]);
    }

    // Recurrent weights in registers: lane j owns gate rows j(i), H+j(f),
    // 2H+j(g), 3H+j(o), packed (i,f) and (g,o) -> 80 regs.
    u64 wif[H], wgo[H];
#pragma unroll
    for (int k = 0; k < H; ++k) {
        wif[k] = pack2(W_hh[j * H + k],           W_hh[(H + j) * H + k]);
        wgo[k] = pack2(W_hh[(2 * H + j) * H + k], W_hh[(3 * H + j) * H + k]);
    }
    const float wl = (lane < H) ? W_lin[lane] : 0.0f;
    const float bl = b_lin[0];

    if (lane < H) hbuf[warp][0][lane] = make_float2(0.0f, 0.0f);
    __syncthreads();   // covers xs + bw + h init

    const u32 bwa = (u32)__cvta_generic_to_shared(&bw[j]);
    float c = 0.0f;
    const float* xrow = xs + warp * SEQ;
    float* ob = out + (size_t)batch * SEQ;

#pragma unroll 1
    for (int t = 0; t < SEQ; ++t) {
        const int rb = t & 1;
        const longlong2* hp = (const longlong2*)&hbuf[warp][rb][0];

        // Per-step reload (asm volatile blocks loop-invariant hoisting ->
        // these 8 values cost 0 persistent registers).
        u64 bif, bgo, wxif, wxgo;
        asm volatile("ld.shared.v2.u64 {%0,%1}, [%2];"
                     : "=l"(bif), "=l"(bgo) : "r"(bwa));
        asm volatile("ld.shared.v2.u64 {%0,%1}, [%2];"
                     : "=l"(wxif), "=l"(wxgo) : "r"(bwa + (u32)(H * 16)));

        float xt = xrow[t];
        u64 x2 = pack2(xt, xt);

        // Single accumulator chain per gate pair (saves regs; 2 chains/warp
        // x 5 warps/SMSP = 10 chains keep the fma pipe throughput-bound).
        u64 aIF = bif, aGO = bgo;
#pragma unroll
        for (int q = 0; q < H / 2; ++q) {
            longlong2 hh = hp[q];        // broadcast LDS.128: {h2q,h2q,h2q+1,h2q+1}
            aIF = fma2((u64)hh.x, wif[2 * q],     aIF);
            aIF = fma2((u64)hh.y, wif[2 * q + 1], aIF);
            aGO = fma2((u64)hh.x, wgo[2 * q],     aGO);
            aGO = fma2((u64)hh.y, wgo[2 * q + 1], aGO);
        }
        u64 gIF = fma2(x2, wxif, aIF);
        u64 gGO = fma2(x2, wxgo, aGO);

        float gi, gf, gg, go;
        unpack2(gIF, gi, gf);
        unpack2(gGO, gg, go);
        float iv = sigmoid_ap(gi);
        float fv = sigmoid_ap(gf);
        float gv = tanh_ap(gg);
        float ov = sigmoid_ap(go);
        c = fmaf(fv, c, iv * gv);
        float h = ov * tanh_ap(c);

        if (lane < H) hbuf[warp][rb ^ 1][lane] = make_float2(h, h);
        __syncwarp();

        // Linear head: butterfly reduce (idle lanes contribute 0 via wl=0).
        float val = h * wl;
#pragma unroll
        for (int off = 16; off; off >>= 1)
            val += __shfl_xor_sync(0xffffffffu, val, off);
        if (lane == 0) ob[t] = val + bl;
    }
}

extern "C" void kernel_launch(void* const* d_in, const int* in_sizes, int n_in,
                              void* d_out, int out_size) {
    const float* x     = (const float*)d_in[0];
    const float* W_ih  = (const float*)d_in[1];
    const float* W_hh  = (const float*)d_in[2];
    const float* b_ih  = (const float*)d_in[3];
    const float* b_hh  = (const float*)d_in[4];
    const float* W_lin = (const float*)d_in[5];
    const float* b_lin = (const float*)d_in[6];
    float* out = (float*)d_out;

    lstm_fused<<<GRID, THREADS>>>(x, W_ih, W_hh, b_ih, b_hh, W_lin, b_lin, out);
}

// round 17
// speedup vs baseline: 1.6758x; 1.6758x over previous
#include <cuda_runtime.h>

#define H     20
#define SEQ   512
#define NB    4096
#define WARPS 4
#define THREADS (WARPS * 32)
#define GRID  (NB / WARPS)     // 1024
#define HP    21               // hist row stride (odd -> bank-conflict-free)

typedef unsigned long long u64;

__device__ __forceinline__ u64 pack2(float a, float b) {
    u64 r; asm("mov.b64 %0, {%1,%2};" : "=l"(r) : "f"(a), "f"(b)); return r;
}
__device__ __forceinline__ void unpack2(u64 v, float& a, float& b) {
    asm("mov.b64 {%0,%1}, %2;" : "=f"(a), "=f"(b) : "l"(v));
}
// Blackwell packed fp32 FMA (f32x2, PTX-only)
__device__ __forceinline__ u64 fma2(u64 a, u64 b, u64 c) {
    u64 d; asm("fma.rn.f32x2 %0, %1, %2, %3;" : "=l"(d) : "l"(a), "l"(b), "l"(c)); return d;
}
__device__ __forceinline__ u64 add2(u64 a, u64 b) {
    u64 d; asm("add.rn.f32x2 %0, %1, %2;" : "=l"(d) : "l"(a), "l"(b)); return d;
}
// HW tanh (MUFU.TANH) — measured safe: rel_err 1.56e-6 over the 512-step recurrence
__device__ __forceinline__ float tanh_ap(float v) {
    float r; asm("tanh.approx.f32 %0, %1;" : "=f"(r) : "f"(v)); return r;
}
__device__ __forceinline__ float sigmoid_ap(float v) {
    return fmaf(0.5f, tanh_ap(0.5f * v), 0.5f);   // FMUL + MUFU + FFMA
}

__global__ __launch_bounds__(THREADS, 4) void lstm_fused(
    const float* __restrict__ x,     const float* __restrict__ W_ih,
    const float* __restrict__ W_hh,  const float* __restrict__ b_ih,
    const float* __restrict__ b_hh,  const float* __restrict__ W_lin,
    const float* __restrict__ b_lin, float* __restrict__ out)
{
    // Per-warp double-buffered h, duplicated {h,h} so LDS.128 feeds fma2.
    __shared__ __align__(16) float2 hbuf[WARPS][2][H];
    // Per-warp head history: hist[time&31][unit] = h*wl. Row stride 21 (odd)
    // -> both the per-step store (lanes=units) and the head-phase reads
    // (lane=time, scan units) are bank-conflict-free.
    __shared__ float hist[WARPS][32][HP];
    __shared__ float xs[WARPS * SEQ];    // staged x rows (8 KB)

    const int warp = threadIdx.x >> 5;
    const int lane = threadIdx.x & 31;
    const int batch = blockIdx.x * WARPS + warp;
    const int j = (lane < H) ? lane : (H - 1);   // clamp idle lanes

    // Coalesced stage of x for all 4 batches of this block.
    for (int i = threadIdx.x; i < WARPS * (SEQ / 4); i += THREADS)
        ((float4*)xs)[i] = ((const float4*)(x + (size_t)blockIdx.x * WARPS * SEQ))[i];

    // Lane j owns hidden unit j: gate rows j(i), H+j(f), 2H+j(g), 3H+j(o).
    // Recurrent weights packed (i,f) and (g,o) -> 80 regs.
    u64 wif[H], wgo[H];
#pragma unroll
    for (int k = 0; k < H; ++k) {
        wif[k] = pack2(W_hh[j * H + k],           W_hh[(H + j) * H + k]);
        wgo[k] = pack2(W_hh[(2 * H + j) * H + k], W_hh[(3 * H + j) * H + k]);
    }
    const u64 bif  = pack2(b_ih[j] + b_hh[j],             b_ih[H + j] + b_hh[H + j]);
    const u64 bgo  = pack2(b_ih[2 * H + j] + b_hh[2 * H + j],
                           b_ih[3 * H + j] + b_hh[3 * H + j]);
    const u64 wxif = pack2(W_ih[j],         W_ih[H + j]);
    const u64 wxgo = pack2(W_ih[2 * H + j], W_ih[3 * H + j]);
    const float wl = (lane < H) ? W_lin[lane] : 0.0f;
    const float bl = b_lin[0];

    if (lane < H) hbuf[warp][0][lane] = make_float2(0.0f, 0.0f);
    __syncthreads();   // covers xs preload + h init

    float c = 0.0f;
    const float* xrow = xs + warp * SEQ;
    float* ob = out + (size_t)batch * SEQ;

#pragma unroll 2
    for (int t = 0; t < SEQ; ++t) {
        const int rb = t & 1;
        const longlong2* hp = (const longlong2*)&hbuf[warp][rb][0];

        float xt = xrow[t];
        u64 x2 = pack2(xt, xt);

        // 4 independent fma2 chains, depth ~10 each.
        u64 aIF = bif, bIF = pack2(0.0f, 0.0f);
        u64 aGO = bgo, bGO = pack2(0.0f, 0.0f);
#pragma unroll
        for (int q = 0; q < H / 2; ++q) {
            longlong2 hh = hp[q];            // broadcast LDS.128: {h2q,h2q,h2q+1,h2q+1}
            u64 h0 = (u64)hh.x, h1 = (u64)hh.y;
            aIF = fma2(h0, wif[2 * q],     aIF);
            bIF = fma2(h1, wif[2 * q + 1], bIF);
            aGO = fma2(h0, wgo[2 * q],     aGO);
            bGO = fma2(h1, wgo[2 * q + 1], bGO);
        }
        u64 gIF = fma2(x2, wxif, add2(aIF, bIF));
        u64 gGO = fma2(x2, wxgo, add2(aGO, bGO));

        float gi, gf, gg, go;
        unpack2(gIF, gi, gf);
        unpack2(gGO, gg, go);
        float iv = sigmoid_ap(gi);
        float fv = sigmoid_ap(gf);
        float gv = tanh_ap(gg);
        float ov = sigmoid_ap(go);
        c = fmaf(fv, c, iv * gv);
        float h = ov * tanh_ap(c);

        if (lane < H) {
            hbuf[warp][rb ^ 1][lane] = make_float2(h, h);
            hist[warp][t & 31][lane] = h * wl;   // head partial: 1 STS vs butterfly
        }
        __syncwarp();

        // Head phase every 32 steps: lane l owns timestep (t-31+l).
        if ((t & 31) == 31) {
            const float* row = &hist[warp][lane][0];
            float a0 = bl, a1 = 0.0f, a2 = 0.0f, a3 = 0.0f;
#pragma unroll
            for (int k = 0; k < H; k += 4) {     // stride-21 rows: conflict-free
                a0 += row[k];
                a1 += row[k + 1];
                a2 += row[k + 2];
                a3 += row[k + 3];
            }
            ob[t - 31 + lane] = (a0 + a1) + (a2 + a3);  // coalesced 128B STG
            __syncwarp();   // hist fully consumed before next phase overwrites
        }
    }
}

extern "C" void kernel_launch(void* const* d_in, const int* in_sizes, int n_in,
                              void* d_out, int out_size) {
    const float* x     = (const float*)d_in[0];
    const float* W_ih  = (const float*)d_in[1];
    const float* W_hh  = (const float*)d_in[2];
    const float* b_ih  = (const float*)d_in[3];
    const float* b_hh  = (const float*)d_in[4];
    const float* W_lin = (const float*)d_in[5];
    const float* b_lin = (const float*)d_in[6];
    float* out = (float*)d_out;

    lstm_fused<<<GRID, THREADS>>>(x, W_ih, W_hh, b_ih, b_hh, W_lin, b_lin, out);
}